// round 11
// baseline (speedup 1.0000x reference)
#include <cuda_runtime.h>
#include <cuda_fp16.h>
#include <cstdint>

// ---------------------------------------------------------------------------
// QuantizedLinear: y = x @ ((q - zp) * s)^T + b
//   y[m,n] = s[n]*(sum_k x*q)/split - s[n]*zp[n]*rowsum_x[m] + b[n]
// R11: int8 tensor path. x = h/16 + l/2048 + eps (h,l int8, |eps|<=2^-12).
// Two s8xs8->s32 mma passes share B fragments; full-K s32 accumulation is
// overflow-safe (<= 66M < 2^31) -> no mid-loop folds. mma.m16n8k32 is a
// base-arch instr (compiles at compute_103, unlike tcgen05).
// Weight buffer arrives as int32 (harness marshalling) — runtime-detected.
// ---------------------------------------------------------------------------

static constexpr int IN_F  = 4096;
static constexpr int OUT_F = 11008;
static constexpr int MROWS = 8192;

static constexpr int BM = 128;
static constexpr int BN = 128;
static constexpr int BK = 128;                // int8 k-elems per iter (128 B rows)
static constexpr int KT = IN_F / BK;          // 32
static constexpr int NSTAGE = 4;

static constexpr int AH_BYTES = BM * BK;      // 16384
static constexpr int B_OFFS   = 2 * AH_BYTES; // A_hi, A_lo, then B
static constexpr int STAGE_BYTES = 3 * AH_BYTES;            // 49152
static constexpr int SMEM_DYN = NSTAGE * STAGE_BYTES;       // 196608

static constexpr int NT = OUT_F / BN;         // 86
static constexpr int MT = MROWS / BM;         // 64
static constexpr int GY = 8;                  // m-band for L2 reuse
static constexpr int PERB = NT * GY;          // 688

// fused-prep block ranges
static constexpr int PREP_W_BLKS = OUT_F;          // 11008
static constexpr int PREP_X_BLKS = MROWS;          // 8192
static constexpr int PREP_C_BLKS = OUT_F / 256;    // 43
static constexpr int PREP_BLKS = PREP_W_BLKS + PREP_X_BLKS + PREP_C_BLKS;

// ---------------- device scratch --------------------------------------------
__device__ __align__(16) int8_t g_Wq[(size_t)OUT_F * IN_F];  // 45 MB
__device__ __align__(16) int8_t g_Ah[(size_t)MROWS * IN_F];  // 33.5 MB
__device__ __align__(16) int8_t g_Al[(size_t)MROWS * IN_F];  // 33.5 MB
__device__ float g_rowsum[MROWS];
__device__ float g_szp[OUT_F];
__device__ int g_w_is_i32;

// ---------------- helpers ----------------------------------------------------
__device__ __forceinline__ uint32_t smem_u32(const void* p) {
    uint32_t a;
    asm("{ .reg .u64 t; cvta.to.shared.u64 t, %1; cvt.u32.u64 %0, t; }"
        : "=r"(a) : "l"(p));
    return a;
}
__device__ __forceinline__ uint32_t sw128(uint32_t o) { return o ^ ((o >> 3) & 0x70u); }

__device__ __forceinline__ void cp16(uint32_t dst, const void* src) {
    asm volatile("cp.async.cg.shared.global [%0], [%1], 16;" :: "r"(dst), "l"(src));
}
__device__ __forceinline__ void cp_commit() {
    asm volatile("cp.async.commit_group;" ::: "memory");
}
template <int N>
__device__ __forceinline__ void cp_wait() {
    asm volatile("cp.async.wait_group %0;" :: "n"(N) : "memory");
}
__device__ __forceinline__ void ldsm4(uint32_t* a, uint32_t addr) {
    asm volatile("ldmatrix.sync.aligned.m8n8.x4.shared.b16 {%0,%1,%2,%3}, [%4];"
                 : "=r"(a[0]), "=r"(a[1]), "=r"(a[2]), "=r"(a[3]) : "r"(addr));
}
// s8 x s8 -> s32, full accumulate (C = D)
__device__ __forceinline__ void mma16832(int* c, const uint32_t* a,
                                         const uint32_t* b) {
    asm volatile(
        "mma.sync.aligned.m16n8k32.row.col.s32.s8.s8.s32 "
        "{%0,%1,%2,%3}, {%4,%5,%6,%7}, {%8,%9}, {%0,%1,%2,%3};"
        : "+r"(c[0]), "+r"(c[1]), "+r"(c[2]), "+r"(c[3])
        : "r"(a[0]), "r"(a[1]), "r"(a[2]), "r"(a[3]), "r"(b[0]), "r"(b[1]));
}

// ---------------- dtype detection --------------------------------------------
__global__ void k_detect_w(const int* __restrict__ q) {
    __shared__ int cnt;
    if (threadIdx.x == 0) cnt = 0;
    __syncthreads();
    int v = q[threadIdx.x];
    if (v >= -128 && v <= 127) atomicAdd(&cnt, 1);
    __syncthreads();
    if (threadIdx.x == 0) g_w_is_i32 = (cnt >= 200) ? 1 : 0;
}

// ---------------- fused prep kernel -------------------------------------------
__global__ void k_prep(const void* __restrict__ qraw,
                       const float* __restrict__ x,
                       const float* __restrict__ sc,
                       const float* __restrict__ zp) {
    const int b = blockIdx.x;
    const int t = threadIdx.x;

    if (b < PREP_W_BLKS) {
        // weight: one block per row; 256 thr x 16 int8
        size_t base = ((size_t)b * 256 + t) * 16;
        if (g_w_is_i32) {
            const int4* p = reinterpret_cast<const int4*>(
                reinterpret_cast<const int*>(qraw) + base);
            int8_t o[16];
#pragma unroll
            for (int u = 0; u < 4; ++u) {
                int4 v = p[u];
                o[u * 4 + 0] = (int8_t)v.x;
                o[u * 4 + 1] = (int8_t)v.y;
                o[u * 4 + 2] = (int8_t)v.z;
                o[u * 4 + 3] = (int8_t)v.w;
            }
            *reinterpret_cast<int4*>(&g_Wq[base]) =
                *reinterpret_cast<const int4*>(o);
        } else {
            *reinterpret_cast<int4*>(&g_Wq[base]) =
                *reinterpret_cast<const int4*>(
                    reinterpret_cast<const int8_t*>(qraw) + base);
        }
        return;
    }

    if (b < PREP_W_BLKS + PREP_X_BLKS) {
        // x split: h = rn(x*16), l = rn((x - h/16)*2048); rowsum of exact x
        const int row = b - PREP_W_BLKS;
        const float4* xr = reinterpret_cast<const float4*>(x + (size_t)row * IN_F);
        float s = 0.f;
#pragma unroll
        for (int j = 0; j < 4; ++j) {
            int idx = t + j * 256;                 // float4 index (1024/row)
            float4 v = xr[idx];
            s += (v.x + v.y) + (v.z + v.w);
            float a[4] = {v.x, v.y, v.z, v.w};
            int8_t hb[4], lb[4];
#pragma unroll
            for (int e = 0; e < 4; ++e) {
                int h = __float2int_rn(a[e] * 16.f);
                h = max(-127, min(127, h));
                int l = __float2int_rn((a[e] - (float)h * 0.0625f) * 2048.f);
                l = max(-127, min(127, l));
                hb[e] = (int8_t)h;
                lb[e] = (int8_t)l;
            }
            size_t off = (size_t)row * IN_F + (size_t)idx * 4;
            *reinterpret_cast<uint32_t*>(&g_Ah[off]) =
                *reinterpret_cast<const uint32_t*>(hb);
            *reinterpret_cast<uint32_t*>(&g_Al[off]) =
                *reinterpret_cast<const uint32_t*>(lb);
        }
#pragma unroll
        for (int o = 16; o > 0; o >>= 1) s += __shfl_xor_sync(0xFFFFFFFFu, s, o);
        __shared__ float ws[8];
        if ((t & 31) == 0) ws[t >> 5] = s;
        __syncthreads();
        if (t == 0) {
            float tot = 0.f;
#pragma unroll
            for (int k = 0; k < 8; ++k) tot += ws[k];
            g_rowsum[row] = tot;
        }
        return;
    }

    int n = (b - PREP_W_BLKS - PREP_X_BLKS) * 256 + t;
    g_szp[n] = sc[n] * zp[n];
}

// ---------------- GEMM (int8, dual-digit, full-K s32 accum) -------------------
__global__ void __launch_bounds__(256, 1)
k_gemm(const float* __restrict__ scale, const float* __restrict__ bias,
       float* __restrict__ out) {
    extern __shared__ __align__(1024) char smem[];
    const uint32_t sb = smem_u32(smem);
    const int tid = threadIdx.x;
    const int wid = tid >> 5;
    const int lane = tid & 31;
    const int mw = wid & 3;        // warp row (0..3), 32 rows each
    const int nw = wid >> 2;       // warp col (0..1), 64 cols each

    // grid swizzle: 8-row m-bands, n fastest within a band
    const int chunk = blockIdx.x / PERB;
    const int rem = blockIdx.x % PERB;
    const int nb = rem / GY;
    const int mb = chunk * GY + (rem % GY);
    const size_t mBase = (size_t)mb * BM;
    const size_t nBase = (size_t)nb * BN;

    const size_t ROWB = (size_t)IN_F;          // int8: 4096 B per row
    const char* gAh = reinterpret_cast<const char*>(g_Ah) + mBase * ROWB;
    const char* gAl = reinterpret_cast<const char*>(g_Al) + mBase * ROWB;
    const char* gB  = reinterpret_cast<const char*>(g_Wq) + nBase * ROWB;

    // per stage: 3 x (128 rows x 128B) = 3 x 1024 xfers over 256 thr
    auto issue_stage = [&](int ki, int slot) {
        uint32_t st = sb + slot * STAGE_BYTES;
        const char* pAh = gAh + (size_t)ki * 128;
        const char* pAl = gAl + (size_t)ki * 128;
        const char* pB  = gB  + (size_t)ki * 128;
#pragma unroll
        for (int u = 0; u < 4; ++u) {
            int v = tid + u * 256;
            int r = v >> 3, sg = v & 7;
            uint32_t so = sw128((uint32_t)(r * 128 + sg * 16));
            size_t go = (size_t)r * ROWB + (size_t)sg * 16;
            cp16(st + so, pAh + go);
            cp16(st + AH_BYTES + so, pAl + go);
            cp16(st + B_OFFS + so, pB + go);
        }
    };

    int accH[2][8][4], accL[2][8][4];
#pragma unroll
    for (int i = 0; i < 2; ++i)
#pragma unroll
        for (int j = 0; j < 8; ++j)
#pragma unroll
            for (int k = 0; k < 4; ++k) { accH[i][j][k] = 0; accL[i][j][k] = 0; }

#pragma unroll
    for (int s = 0; s < NSTAGE - 1; ++s) { issue_stage(s, s); cp_commit(); }

    // A frags: row = mw*32 + mi*16 + (lane&15); 16B seg = 16 k-bytes (lane>>4)
    const uint32_t aOff = (uint32_t)(mw * 32 + (lane & 15)) * 128 + ((lane >> 4) << 4);
    // B frags: g4 = lane>>3: (n0-7,kb0-15),(n0-7,kb16-31),(n8-15,kb0-15),(n8-15,kb16-31)
    const uint32_t g4 = (uint32_t)(lane >> 3);
    const uint32_t bOff =
        (uint32_t)(nw * 64 + ((g4 >> 1) << 3) + (lane & 7)) * 128 + ((g4 & 1) << 4);

#pragma unroll 1
    for (int k = 0; k < KT; ++k) {
        cp_wait<NSTAGE - 2>();
        __syncthreads();
        if (k + NSTAGE - 1 < KT) {
            int kn = k + NSTAGE - 1;
            issue_stage(kn, kn % NSTAGE);
        }
        cp_commit();

        const uint32_t st = sb + (uint32_t)(k % NSTAGE) * STAGE_BYTES;
#pragma unroll
        for (int ks = 0; ks < 4; ++ks) {   // 32 k-bytes per ks
            uint32_t ah[2][4], al[2][4], b[4][4];
#pragma unroll
            for (int mi = 0; mi < 2; ++mi) {
                uint32_t ao = sw128(aOff + (uint32_t)(mi * 2048 + ks * 32));
                ldsm4(ah[mi], st + ao);
                ldsm4(al[mi], st + AH_BYTES + ao);
            }
#pragma unroll
            for (int p = 0; p < 4; ++p)
                ldsm4(b[p],
                      st + B_OFFS + sw128(bOff + (uint32_t)(p * 2048 + ks * 32)));
#pragma unroll
            for (int mi = 0; mi < 2; ++mi)
#pragma unroll
                for (int p = 0; p < 4; ++p) {
                    mma16832(accH[mi][p * 2 + 0], ah[mi], &b[p][0]);
                    mma16832(accH[mi][p * 2 + 1], ah[mi], &b[p][2]);
                    mma16832(accL[mi][p * 2 + 0], al[mi], &b[p][0]);
                    mma16832(accL[mi][p * 2 + 1], al[mi], &b[p][2]);
                }
        }
    }

    __syncthreads();

    // epilogue coefficients in (now free) smem
    float* sSc = reinterpret_cast<float*>(smem);
    float* sZp = sSc + BN;
    float* sBi = sZp + BN;
    for (int v = tid; v < BN; v += 256) {
        int n = (int)nBase + v;
        sSc[v] = scale[n];
        sZp[v] = g_szp[n];
        sBi[v] = bias[n];
    }
    __syncthreads();

    const int rBase = (int)mBase + mw * 32 + (lane >> 2);
    const int cq = (lane & 3) * 2;
#pragma unroll
    for (int mi = 0; mi < 2; ++mi) {
        const int r0 = rBase + mi * 16;
        const float rs0 = g_rowsum[r0];
        const float rs1 = g_rowsum[r0 + 8];
        float* o0 = out + (size_t)r0 * OUT_F + nBase;
        float* o1 = out + (size_t)(r0 + 8) * OUT_F + nBase;
#pragma unroll
        for (int p = 0; p < 4; ++p) {
#pragma unroll
            for (int h = 0; h < 2; ++h) {
                const int* cH = accH[mi][p * 2 + h];
                const int* cL = accL[mi][p * 2 + h];
                const int col = nw * 64 + p * 16 + h * 8 + cq;
                const float sH0 = sSc[col] * 0.0625f;          // s/16
                const float sL0 = sSc[col] * 4.8828125e-4f;    // s/2048
                const float sH1 = sSc[col + 1] * 0.0625f;
                const float sL1 = sSc[col + 1] * 4.8828125e-4f;
                const float c00 = fmaf(-rs0, sZp[col],     sBi[col]);
                const float c01 = fmaf(-rs0, sZp[col + 1], sBi[col + 1]);
                const float c10 = fmaf(-rs1, sZp[col],     sBi[col]);
                const float c11 = fmaf(-rs1, sZp[col + 1], sBi[col + 1]);
                float2 v0, v1;
                v0.x = fmaf((float)cH[0], sH0, fmaf((float)cL[0], sL0, c00));
                v0.y = fmaf((float)cH[1], sH1, fmaf((float)cL[1], sL1, c01));
                v1.x = fmaf((float)cH[2], sH0, fmaf((float)cL[2], sL0, c10));
                v1.y = fmaf((float)cH[3], sH1, fmaf((float)cL[3], sL1, c11));
                *reinterpret_cast<float2*>(o0 + col) = v0;
                *reinterpret_cast<float2*>(o1 + col) = v1;
            }
        }
    }
}

// ---------------- launch -------------------------------------------------------
extern "C" void kernel_launch(void* const* d_in, const int* in_sizes, int n_in,
                              void* d_out, int out_size) {
    const float* x  = (const float*)d_in[0];
    const void*  q  = d_in[1];
    const float* sc = (const float*)d_in[2];
    const float* zp = (const float*)d_in[3];
    const float* bi = (const float*)d_in[4];
    float* out = (float*)d_out;

    k_detect_w<<<1, 256>>>((const int*)q);
    k_prep<<<PREP_BLKS, 256>>>(q, x, sc, zp);

    cudaFuncSetAttribute(k_gemm, cudaFuncAttributeMaxDynamicSharedMemorySize, SMEM_DYN);
    k_gemm<<<NT * MT, 256, SMEM_DYN>>>(sc, bi, out);
}

// round 12
// speedup vs baseline: 4.8283x; 4.8283x over previous
#include <cuda_runtime.h>
#include <cuda_fp16.h>
#include <cstdint>

// ---------------------------------------------------------------------------
// QuantizedLinear: y = x @ ((q - zp) * s)^T + b
//   y[m,n] = s[n] * (sum_k x[m,k]*q[n,k]) - s[n]*zp[n]*rowsum_x[m] + b[n]
// fp16 GEMM via mma.sync.m16n8k16 with **f16 accumulators** (2x issue rate on
// archs where fp16-acc is double-pumped), folded to f32 master accumulators
// every 64-k iteration (accumulation error ~2e-4, combined ~3.5e-4 < 1e-3).
// R12 = R10 structure (128x128 tile, 256 thr, 3 stages, 2 CTAs/SM).
// Weight buffer arrives as int32 (harness marshalling) — runtime-detected.
// ---------------------------------------------------------------------------

static constexpr int IN_F  = 4096;
static constexpr int OUT_F = 11008;
static constexpr int MROWS = 8192;

static constexpr int BM = 128;
static constexpr int BN = 128;
static constexpr int BK = 64;                 // halves per k-chunk (128 B rows)
static constexpr int KT = IN_F / BK;          // 64
static constexpr int NSTAGE = 3;

static constexpr int A_BYTES = BM * BK * 2;   // 16384
static constexpr int B_BYTES = BN * BK * 2;   // 16384
static constexpr int STAGE_BYTES = A_BYTES + B_BYTES;       // 32768
static constexpr int SMEM_DYN = NSTAGE * STAGE_BYTES;       // 98304 (x2 CTAs)

static constexpr int NT = OUT_F / BN;         // 86
static constexpr int MT = MROWS / BM;         // 64
static constexpr int GY = 8;                  // m-band for L2 reuse
static constexpr int PERB = NT * GY;          // 688

// fused-prep block ranges
static constexpr int PREP_W_BLKS = OUT_F;          // 11008
static constexpr int PREP_X_BLKS = MROWS;          // 8192
static constexpr int PREP_C_BLKS = OUT_F / 256;    // 43
static constexpr int PREP_BLKS = PREP_W_BLKS + PREP_X_BLKS + PREP_C_BLKS;

// ---------------- device scratch --------------------------------------------
__device__ __align__(16) __half g_W[(size_t)OUT_F * IN_F];   // ~90 MB
__device__ __align__(16) __half g_A[(size_t)MROWS * IN_F];   // ~67 MB
__device__ float g_rowsum[MROWS];
__device__ float g_szp[OUT_F];
__device__ int g_w_is_i32;

// ---------------- helpers ----------------------------------------------------
__device__ __forceinline__ uint32_t smem_u32(const void* p) {
    uint32_t a;
    asm("{ .reg .u64 t; cvta.to.shared.u64 t, %1; cvt.u32.u64 %0, t; }"
        : "=r"(a) : "l"(p));
    return a;
}
__device__ __forceinline__ uint32_t sw128(uint32_t o) { return o ^ ((o >> 3) & 0x70u); }

__device__ __forceinline__ void cp16(uint32_t dst, const void* src) {
    asm volatile("cp.async.cg.shared.global [%0], [%1], 16;" :: "r"(dst), "l"(src));
}
__device__ __forceinline__ void cp_commit() {
    asm volatile("cp.async.commit_group;" ::: "memory");
}
template <int N>
__device__ __forceinline__ void cp_wait() {
    asm volatile("cp.async.wait_group %0;" :: "n"(N) : "memory");
}
__device__ __forceinline__ void ldsm4(uint32_t* a, uint32_t addr) {
    asm volatile("ldmatrix.sync.aligned.m8n8.x4.shared.b16 {%0,%1,%2,%3}, [%4];"
                 : "=r"(a[0]), "=r"(a[1]), "=r"(a[2]), "=r"(a[3]) : "r"(addr));
}
// f16 x f16 -> f16 accumulate: D{d0,d1} = A*B + C ; d0 = rows lane>>2,
// cols (lane&3)*2+{0,1} (f16x2), d1 = rows +8.  Same cell mapping as f32 acc.
__device__ __forceinline__ void mma16816h(uint32_t* c, const uint32_t* a,
                                          const uint32_t* b) {
    asm volatile(
        "mma.sync.aligned.m16n8k16.row.col.f16.f16.f16.f16 "
        "{%0,%1}, {%2,%3,%4,%5}, {%6,%7}, {%0,%1};"
        : "+r"(c[0]), "+r"(c[1])
        : "r"(a[0]), "r"(a[1]), "r"(a[2]), "r"(a[3]), "r"(b[0]), "r"(b[1]));
}

// ---------------- dtype detection --------------------------------------------
__global__ void k_detect_w(const int* __restrict__ q) {
    __shared__ int cnt;
    if (threadIdx.x == 0) cnt = 0;
    __syncthreads();
    int v = q[threadIdx.x];
    if (v >= -128 && v <= 127) atomicAdd(&cnt, 1);
    __syncthreads();
    if (threadIdx.x == 0) g_w_is_i32 = (cnt >= 200) ? 1 : 0;
}

// ---------------- fused prep kernel -------------------------------------------
__global__ void k_prep(const void* __restrict__ qraw,
                       const float* __restrict__ x,
                       const float* __restrict__ sc,
                       const float* __restrict__ zp) {
    const int b = blockIdx.x;
    const int t = threadIdx.x;

    if (b < PREP_W_BLKS) {
        size_t base = ((size_t)b * 256 + t) * 16;
        __half o[16];
        if (g_w_is_i32) {
            const int4* p = reinterpret_cast<const int4*>(
                reinterpret_cast<const int*>(qraw) + base);
#pragma unroll
            for (int u = 0; u < 4; ++u) {
                int4 v = p[u];
                o[u * 4 + 0] = __float2half_rn((float)v.x);
                o[u * 4 + 1] = __float2half_rn((float)v.y);
                o[u * 4 + 2] = __float2half_rn((float)v.z);
                o[u * 4 + 3] = __float2half_rn((float)v.w);
            }
        } else {
            int4 v = *reinterpret_cast<const int4*>(
                reinterpret_cast<const int8_t*>(qraw) + base);
            const int8_t* c = reinterpret_cast<const int8_t*>(&v);
#pragma unroll
            for (int k = 0; k < 16; ++k) o[k] = __float2half_rn((float)c[k]);
        }
        *reinterpret_cast<int4*>(&g_W[base])     = *reinterpret_cast<const int4*>(&o[0]);
        *reinterpret_cast<int4*>(&g_W[base + 8]) = *reinterpret_cast<const int4*>(&o[8]);
        return;
    }

    if (b < PREP_W_BLKS + PREP_X_BLKS) {
        const int row = b - PREP_W_BLKS;
        const float4* xr = reinterpret_cast<const float4*>(x + (size_t)row * IN_F);
        float s = 0.f;
#pragma unroll
        for (int j = 0; j < 4; ++j) {
            int idx = t + j * 256;
            float4 v = xr[idx];
            s += (v.x + v.y) + (v.z + v.w);
            __half h[4] = {__float2half_rn(v.x), __float2half_rn(v.y),
                           __float2half_rn(v.z), __float2half_rn(v.w)};
            *reinterpret_cast<uint2*>(&g_A[(size_t)row * IN_F + (size_t)idx * 4]) =
                *reinterpret_cast<const uint2*>(h);
        }
#pragma unroll
        for (int o = 16; o > 0; o >>= 1) s += __shfl_xor_sync(0xFFFFFFFFu, s, o);
        __shared__ float ws[8];
        if ((t & 31) == 0) ws[t >> 5] = s;
        __syncthreads();
        if (t == 0) {
            float tot = 0.f;
#pragma unroll
            for (int k = 0; k < 8; ++k) tot += ws[k];
            g_rowsum[row] = tot;
        }
        return;
    }

    int n = (b - PREP_W_BLKS - PREP_X_BLKS) * 256 + t;
    g_szp[n] = sc[n] * zp[n];
}

// ---------------- GEMM ---------------------------------------------------------
__global__ void __launch_bounds__(256, 2)
k_gemm(const float* __restrict__ scale, const float* __restrict__ bias,
       float* __restrict__ out) {
    extern __shared__ __align__(1024) char smem[];
    const uint32_t sb = smem_u32(smem);
    const int tid = threadIdx.x;
    const int wid = tid >> 5;
    const int lane = tid & 31;
    const int mw = wid & 3;        // warp row (0..3), 32 rows each
    const int nw = wid >> 2;       // warp col (0..1), 64 cols each

    // grid swizzle: 8-row m-bands, n fastest within a band
    const int chunk = blockIdx.x / PERB;
    const int rem = blockIdx.x % PERB;
    const int nb = rem / GY;
    const int mb = chunk * GY + (rem % GY);
    const size_t mBase = (size_t)mb * BM;
    const size_t nBase = (size_t)nb * BN;

    const size_t ROWB = (size_t)IN_F * 2;      // bytes per gmem row
    const char* gA = reinterpret_cast<const char*>(g_A) + mBase * ROWB;
    const char* gB = reinterpret_cast<const char*>(g_W) + nBase * ROWB;

    auto issue_stage = [&](int ki, int slot) {
        uint32_t st = sb + slot * STAGE_BYTES;
        const char* pA = gA + (size_t)ki * 128;
        const char* pB = gB + (size_t)ki * 128;
#pragma unroll
        for (int u = 0; u < 4; ++u) {
            int v = tid + u * 256;
            int r = v >> 3, sg = v & 7;
            uint32_t so = sw128((uint32_t)(r * 128 + sg * 16));
            size_t go = (size_t)r * ROWB + (size_t)sg * 16;
            cp16(st + so, pA + go);
            cp16(st + A_BYTES + so, pB + go);
        }
    };

    float acc[2][8][4];     // f32 master accumulators
#pragma unroll
    for (int i = 0; i < 2; ++i)
#pragma unroll
        for (int j = 0; j < 8; ++j)
#pragma unroll
            for (int k = 0; k < 4; ++k) acc[i][j][k] = 0.f;

#pragma unroll
    for (int s = 0; s < NSTAGE - 1; ++s) { issue_stage(s, s); cp_commit(); }

    // A frags (x4 non-trans): row = mw*32 + mi*16 + (lane&15), khalf = lane>>4
    const uint32_t aOff = (uint32_t)(mw * 32 + (lane & 15)) * 128 + ((lane >> 4) << 4);
    // B frags (x4 non-trans): g=lane>>3 ->
    //   (n0-7,k0-7),(n0-7,k8-15),(n8-15,k0-7),(n8-15,k8-15)
    const uint32_t g4 = (uint32_t)(lane >> 3);
    const uint32_t bOff =
        (uint32_t)(nw * 64 + ((g4 >> 1) << 3) + (lane & 7)) * 128 + ((g4 & 1) << 4);

#pragma unroll 1
    for (int k = 0; k < KT; ++k) {
        cp_wait<NSTAGE - 2>();
        __syncthreads();
        if (k + NSTAGE - 1 < KT) {
            int kn = k + NSTAGE - 1;
            issue_stage(kn, kn % NSTAGE);
        }
        cp_commit();

        // fresh f16 accumulators for this 64-k iteration
        uint32_t hacc[2][8][2];
#pragma unroll
        for (int i = 0; i < 2; ++i)
#pragma unroll
            for (int j = 0; j < 8; ++j) { hacc[i][j][0] = 0u; hacc[i][j][1] = 0u; }

        const uint32_t st = sb + (uint32_t)(k % NSTAGE) * STAGE_BYTES;
#pragma unroll
        for (int ks = 0; ks < 4; ++ks) {
            uint32_t a[2][4];
#pragma unroll
            for (int mi = 0; mi < 2; ++mi)
                ldsm4(a[mi], st + sw128(aOff + (uint32_t)(mi * 2048 + ks * 32)));
            uint32_t b[4][4];
#pragma unroll
            for (int p = 0; p < 4; ++p)
                ldsm4(b[p],
                      st + A_BYTES + sw128(bOff + (uint32_t)(p * 2048 + ks * 32)));
#pragma unroll
            for (int mi = 0; mi < 2; ++mi)
#pragma unroll
                for (int p = 0; p < 4; ++p) {
                    mma16816h(hacc[mi][p * 2 + 0], a[mi], &b[p][0]);
                    mma16816h(hacc[mi][p * 2 + 1], a[mi], &b[p][2]);
                }
        }

        // fold f16 partials into f32 masters (fma pipe, overlaps tensor pipe)
#pragma unroll
        for (int mi = 0; mi < 2; ++mi)
#pragma unroll
            for (int j = 0; j < 8; ++j) {
                float2 lo = __half22float2(
                    *reinterpret_cast<const __half2*>(&hacc[mi][j][0]));
                float2 hi = __half22float2(
                    *reinterpret_cast<const __half2*>(&hacc[mi][j][1]));
                acc[mi][j][0] += lo.x;
                acc[mi][j][1] += lo.y;
                acc[mi][j][2] += hi.x;
                acc[mi][j][3] += hi.y;
            }
    }

    __syncthreads();

    // epilogue coefficients in (now free) smem
    float* sSc = reinterpret_cast<float*>(smem);
    float* sZp = sSc + BN;
    float* sBi = sZp + BN;
    for (int v = tid; v < BN; v += 256) {
        int n = (int)nBase + v;
        sSc[v] = scale[n];
        sZp[v] = g_szp[n];
        sBi[v] = bias[n];
    }
    __syncthreads();

    const int rBase = (int)mBase + mw * 32 + (lane >> 2);
    const int cq = (lane & 3) * 2;
#pragma unroll
    for (int mi = 0; mi < 2; ++mi) {
        const int r0 = rBase + mi * 16;
        const float rs0 = g_rowsum[r0];
        const float rs1 = g_rowsum[r0 + 8];
        float* o0 = out + (size_t)r0 * OUT_F + nBase;
        float* o1 = out + (size_t)(r0 + 8) * OUT_F + nBase;
#pragma unroll
        for (int p = 0; p < 4; ++p) {
#pragma unroll
            for (int h = 0; h < 2; ++h) {
                const float* c = acc[mi][p * 2 + h];
                const int col = nw * 64 + p * 16 + h * 8 + cq;
                float2 v0, v1;
                v0.x = fmaf(c[0], sSc[col],     fmaf(-rs0, sZp[col],     sBi[col]));
                v0.y = fmaf(c[1], sSc[col + 1], fmaf(-rs0, sZp[col + 1], sBi[col + 1]));
                v1.x = fmaf(c[2], sSc[col],     fmaf(-rs1, sZp[col],     sBi[col]));
                v1.y = fmaf(c[3], sSc[col + 1], fmaf(-rs1, sZp[col + 1], sBi[col + 1]));
                *reinterpret_cast<float2*>(o0 + col) = v0;
                *reinterpret_cast<float2*>(o1 + col) = v1;
            }
        }
    }
}

// ---------------- launch -------------------------------------------------------
extern "C" void kernel_launch(void* const* d_in, const int* in_sizes, int n_in,
                              void* d_out, int out_size) {
    const float* x  = (const float*)d_in[0];
    const void*  q  = d_in[1];
    const float* sc = (const float*)d_in[2];
    const float* zp = (const float*)d_in[3];
    const float* bi = (const float*)d_in[4];
    float* out = (float*)d_out;

    k_detect_w<<<1, 256>>>((const int*)q);
    k_prep<<<PREP_BLKS, 256>>>(q, x, sc, zp);

    cudaFuncSetAttribute(k_gemm, cudaFuncAttributeMaxDynamicSharedMemorySize, SMEM_DYN);
    k_gemm<<<NT * MT, 256, SMEM_DYN>>>(sc, bi, out);
}

// round 13
// speedup vs baseline: 5.8567x; 1.2130x over previous
#include <cuda_runtime.h>
#include <cuda_fp16.h>
#include <cstdint>

// ---------------------------------------------------------------------------
// QuantizedLinear: y = x @ ((q - zp) * s)^T + b
//   y[m,n] = s[n] * (sum_k x[m,k]*q[n,k]) - s[n]*zp[n]*rowsum_x[m] + b[n]
// fp16 single-pass GEMM (q exact in fp16, x rounding ~2^-11), f32 accum via
// mma.sync.m16n8k16 (base-arch features; tcgen05 rejected at compute_103).
// R13 = R10 (best: 1597us) + (a) ks=0 fragment loads issued BEFORE the
// next-stage cp.async burst (LSU-port ordering: tensor pipe starts ~100cyc
// earlier per iter), (b) GY=16 halves W DRAM re-reads.
// Weight buffer arrives as int32 (harness marshalling) — runtime-detected.
// ---------------------------------------------------------------------------

static constexpr int IN_F  = 4096;
static constexpr int OUT_F = 11008;
static constexpr int MROWS = 8192;

static constexpr int BM = 128;
static constexpr int BN = 128;
static constexpr int BK = 64;                 // halves per k-chunk (128 B rows)
static constexpr int KT = IN_F / BK;          // 64
static constexpr int NSTAGE = 3;

static constexpr int A_BYTES = BM * BK * 2;   // 16384
static constexpr int B_BYTES = BN * BK * 2;   // 16384
static constexpr int STAGE_BYTES = A_BYTES + B_BYTES;       // 32768
static constexpr int SMEM_DYN = NSTAGE * STAGE_BYTES;       // 98304 (x2 CTAs)

static constexpr int NT = OUT_F / BN;         // 86
static constexpr int MT = MROWS / BM;         // 64
static constexpr int GY = 16;                 // m-band for L2 reuse
static constexpr int PERB = NT * GY;          // 1376

// fused-prep block ranges
static constexpr int PREP_W_BLKS = OUT_F;          // 11008
static constexpr int PREP_X_BLKS = MROWS;          // 8192
static constexpr int PREP_C_BLKS = OUT_F / 256;    // 43
static constexpr int PREP_BLKS = PREP_W_BLKS + PREP_X_BLKS + PREP_C_BLKS;

// ---------------- device scratch --------------------------------------------
__device__ __align__(16) __half g_W[(size_t)OUT_F * IN_F];   // ~90 MB
__device__ __align__(16) __half g_A[(size_t)MROWS * IN_F];   // ~67 MB
__device__ float g_rowsum[MROWS];
__device__ float g_szp[OUT_F];
__device__ int g_w_is_i32;

// ---------------- helpers ----------------------------------------------------
__device__ __forceinline__ uint32_t smem_u32(const void* p) {
    uint32_t a;
    asm("{ .reg .u64 t; cvta.to.shared.u64 t, %1; cvt.u32.u64 %0, t; }"
        : "=r"(a) : "l"(p));
    return a;
}
__device__ __forceinline__ uint32_t sw128(uint32_t o) { return o ^ ((o >> 3) & 0x70u); }

__device__ __forceinline__ void cp16(uint32_t dst, const void* src) {
    asm volatile("cp.async.cg.shared.global [%0], [%1], 16;" :: "r"(dst), "l"(src));
}
__device__ __forceinline__ void cp_commit() {
    asm volatile("cp.async.commit_group;" ::: "memory");
}
template <int N>
__device__ __forceinline__ void cp_wait() {
    asm volatile("cp.async.wait_group %0;" :: "n"(N) : "memory");
}
__device__ __forceinline__ void ldsm4(uint32_t* a, uint32_t addr) {
    asm volatile("ldmatrix.sync.aligned.m8n8.x4.shared.b16 {%0,%1,%2,%3}, [%4];"
                 : "=r"(a[0]), "=r"(a[1]), "=r"(a[2]), "=r"(a[3]) : "r"(addr));
}
__device__ __forceinline__ void mma16816(float* c, const uint32_t* a,
                                         const uint32_t* b) {
    asm volatile(
        "mma.sync.aligned.m16n8k16.row.col.f32.f16.f16.f32 "
        "{%0,%1,%2,%3}, {%4,%5,%6,%7}, {%8,%9}, {%0,%1,%2,%3};"
        : "+f"(c[0]), "+f"(c[1]), "+f"(c[2]), "+f"(c[3])
        : "r"(a[0]), "r"(a[1]), "r"(a[2]), "r"(a[3]), "r"(b[0]), "r"(b[1]));
}

// ---------------- dtype detection --------------------------------------------
__global__ void k_detect_w(const int* __restrict__ q) {
    __shared__ int cnt;
    if (threadIdx.x == 0) cnt = 0;
    __syncthreads();
    int v = q[threadIdx.x];
    if (v >= -128 && v <= 127) atomicAdd(&cnt, 1);
    __syncthreads();
    if (threadIdx.x == 0) g_w_is_i32 = (cnt >= 200) ? 1 : 0;
}

// ---------------- fused prep kernel -------------------------------------------
__global__ void k_prep(const void* __restrict__ qraw,
                       const float* __restrict__ x,
                       const float* __restrict__ sc,
                       const float* __restrict__ zp) {
    const int b = blockIdx.x;
    const int t = threadIdx.x;

    if (b < PREP_W_BLKS) {
        size_t base = ((size_t)b * 256 + t) * 16;
        __half o[16];
        if (g_w_is_i32) {
            const int4* p = reinterpret_cast<const int4*>(
                reinterpret_cast<const int*>(qraw) + base);
#pragma unroll
            for (int u = 0; u < 4; ++u) {
                int4 v = p[u];
                o[u * 4 + 0] = __float2half_rn((float)v.x);
                o[u * 4 + 1] = __float2half_rn((float)v.y);
                o[u * 4 + 2] = __float2half_rn((float)v.z);
                o[u * 4 + 3] = __float2half_rn((float)v.w);
            }
        } else {
            int4 v = *reinterpret_cast<const int4*>(
                reinterpret_cast<const int8_t*>(qraw) + base);
            const int8_t* c = reinterpret_cast<const int8_t*>(&v);
#pragma unroll
            for (int k = 0; k < 16; ++k) o[k] = __float2half_rn((float)c[k]);
        }
        *reinterpret_cast<int4*>(&g_W[base])     = *reinterpret_cast<const int4*>(&o[0]);
        *reinterpret_cast<int4*>(&g_W[base + 8]) = *reinterpret_cast<const int4*>(&o[8]);
        return;
    }

    if (b < PREP_W_BLKS + PREP_X_BLKS) {
        const int row = b - PREP_W_BLKS;
        const float4* xr = reinterpret_cast<const float4*>(x + (size_t)row * IN_F);
        float s = 0.f;
#pragma unroll
        for (int j = 0; j < 4; ++j) {
            int idx = t + j * 256;
            float4 v = xr[idx];
            s += (v.x + v.y) + (v.z + v.w);
            __half h[4] = {__float2half_rn(v.x), __float2half_rn(v.y),
                           __float2half_rn(v.z), __float2half_rn(v.w)};
            *reinterpret_cast<uint2*>(&g_A[(size_t)row * IN_F + (size_t)idx * 4]) =
                *reinterpret_cast<const uint2*>(h);
        }
#pragma unroll
        for (int o = 16; o > 0; o >>= 1) s += __shfl_xor_sync(0xFFFFFFFFu, s, o);
        __shared__ float ws[8];
        if ((t & 31) == 0) ws[t >> 5] = s;
        __syncthreads();
        if (t == 0) {
            float tot = 0.f;
#pragma unroll
            for (int k = 0; k < 8; ++k) tot += ws[k];
            g_rowsum[row] = tot;
        }
        return;
    }

    int n = (b - PREP_W_BLKS - PREP_X_BLKS) * 256 + t;
    g_szp[n] = sc[n] * zp[n];
}

// ---------------- GEMM ---------------------------------------------------------
__global__ void __launch_bounds__(256, 2)
k_gemm(const float* __restrict__ scale, const float* __restrict__ bias,
       float* __restrict__ out) {
    extern __shared__ __align__(1024) char smem[];
    const uint32_t sb = smem_u32(smem);
    const int tid = threadIdx.x;
    const int wid = tid >> 5;
    const int lane = tid & 31;
    const int mw = wid & 3;        // warp row (0..3), 32 rows each
    const int nw = wid >> 2;       // warp col (0..1), 64 cols each

    // grid swizzle: 16-row m-bands, n fastest within a band
    const int chunk = blockIdx.x / PERB;
    const int rem = blockIdx.x % PERB;
    const int nb = rem / GY;
    const int mb = chunk * GY + (rem % GY);
    const size_t mBase = (size_t)mb * BM;
    const size_t nBase = (size_t)nb * BN;

    const size_t ROWB = (size_t)IN_F * 2;      // bytes per gmem row
    const char* gA = reinterpret_cast<const char*>(g_A) + mBase * ROWB;
    const char* gB = reinterpret_cast<const char*>(g_W) + nBase * ROWB;

    auto issue_stage = [&](int ki, int slot) {
        uint32_t st = sb + slot * STAGE_BYTES;
        const char* pA = gA + (size_t)ki * 128;
        const char* pB = gB + (size_t)ki * 128;
#pragma unroll
        for (int u = 0; u < 4; ++u) {
            int v = tid + u * 256;
            int r = v >> 3, sg = v & 7;
            uint32_t so = sw128((uint32_t)(r * 128 + sg * 16));
            size_t go = (size_t)r * ROWB + (size_t)sg * 16;
            cp16(st + so, pA + go);
            cp16(st + A_BYTES + so, pB + go);
        }
    };

    float acc[2][8][4];
#pragma unroll
    for (int i = 0; i < 2; ++i)
#pragma unroll
        for (int j = 0; j < 8; ++j)
#pragma unroll
            for (int k = 0; k < 4; ++k) acc[i][j][k] = 0.f;

#pragma unroll
    for (int s = 0; s < NSTAGE - 1; ++s) { issue_stage(s, s); cp_commit(); }

    // A frags (x4 non-trans): row = mw*32 + mi*16 + (lane&15), khalf = lane>>4
    const uint32_t aOff = (uint32_t)(mw * 32 + (lane & 15)) * 128 + ((lane >> 4) << 4);
    // B frags (x4 non-trans): g=lane>>3 ->
    //   (n0-7,k0-7),(n0-7,k8-15),(n8-15,k0-7),(n8-15,k8-15)
    const uint32_t g4 = (uint32_t)(lane >> 3);
    const uint32_t bOff =
        (uint32_t)(nw * 64 + ((g4 >> 1) << 3) + (lane & 7)) * 128 + ((g4 & 1) << 4);

#pragma unroll 1
    for (int k = 0; k < KT; ++k) {
        cp_wait<NSTAGE - 2>();
        __syncthreads();

        const uint32_t st = sb + (uint32_t)(k % NSTAGE) * STAGE_BYTES;

        // ---- ks=0 fragment loads FIRST: tensor pipe starts before the
        //      next-stage cp.async burst occupies the LSU port.
        uint32_t a0[2][4], b0[4][4];
#pragma unroll
        for (int mi = 0; mi < 2; ++mi)
            ldsm4(a0[mi], st + sw128(aOff + (uint32_t)(mi * 2048)));
#pragma unroll
        for (int p = 0; p < 4; ++p)
            ldsm4(b0[p], st + A_BYTES + sw128(bOff + (uint32_t)(p * 2048)));

        if (k + NSTAGE - 1 < KT) {
            int kn = k + NSTAGE - 1;
            issue_stage(kn, kn % NSTAGE);
        }
        cp_commit();

        // ks = 0 MMAs
#pragma unroll
        for (int mi = 0; mi < 2; ++mi)
#pragma unroll
            for (int p = 0; p < 4; ++p) {
                mma16816(acc[mi][p * 2 + 0], a0[mi], &b0[p][0]);
                mma16816(acc[mi][p * 2 + 1], a0[mi], &b0[p][2]);
            }

        // ks = 1..3
#pragma unroll
        for (int ks = 1; ks < 4; ++ks) {
            uint32_t a[2][4];
#pragma unroll
            for (int mi = 0; mi < 2; ++mi)
                ldsm4(a[mi], st + sw128(aOff + (uint32_t)(mi * 2048 + ks * 32)));
            uint32_t b[4][4];
#pragma unroll
            for (int p = 0; p < 4; ++p)
                ldsm4(b[p],
                      st + A_BYTES + sw128(bOff + (uint32_t)(p * 2048 + ks * 32)));
#pragma unroll
            for (int mi = 0; mi < 2; ++mi)
#pragma unroll
                for (int p = 0; p < 4; ++p) {
                    mma16816(acc[mi][p * 2 + 0], a[mi], &b[p][0]);
                    mma16816(acc[mi][p * 2 + 1], a[mi], &b[p][2]);
                }
        }
    }

    __syncthreads();

    // epilogue coefficients in (now free) smem
    float* sSc = reinterpret_cast<float*>(smem);
    float* sZp = sSc + BN;
    float* sBi = sZp + BN;
    for (int v = tid; v < BN; v += 256) {
        int n = (int)nBase + v;
        sSc[v] = scale[n];
        sZp[v] = g_szp[n];
        sBi[v] = bias[n];
    }
    __syncthreads();

    const int rBase = (int)mBase + mw * 32 + (lane >> 2);
    const int cq = (lane & 3) * 2;
#pragma unroll
    for (int mi = 0; mi < 2; ++mi) {
        const int r0 = rBase + mi * 16;
        const float rs0 = g_rowsum[r0];
        const float rs1 = g_rowsum[r0 + 8];
        float* o0 = out + (size_t)r0 * OUT_F + nBase;
        float* o1 = out + (size_t)(r0 + 8) * OUT_F + nBase;
#pragma unroll
        for (int p = 0; p < 4; ++p) {
#pragma unroll
            for (int h = 0; h < 2; ++h) {
                const float* c = acc[mi][p * 2 + h];
                const int col = nw * 64 + p * 16 + h * 8 + cq;
                float2 v0, v1;
                v0.x = fmaf(c[0], sSc[col],     fmaf(-rs0, sZp[col],     sBi[col]));
                v0.y = fmaf(c[1], sSc[col + 1], fmaf(-rs0, sZp[col + 1], sBi[col + 1]));
                v1.x = fmaf(c[2], sSc[col],     fmaf(-rs1, sZp[col],     sBi[col]));
                v1.y = fmaf(c[3], sSc[col + 1], fmaf(-rs1, sZp[col + 1], sBi[col + 1]));
                *reinterpret_cast<float2*>(o0 + col) = v0;
                *reinterpret_cast<float2*>(o1 + col) = v1;
            }
        }
    }
}

// ---------------- launch -------------------------------------------------------
extern "C" void kernel_launch(void* const* d_in, const int* in_sizes, int n_in,
                              void* d_out, int out_size) {
    const float* x  = (const float*)d_in[0];
    const void*  q  = d_in[1];
    const float* sc = (const float*)d_in[2];
    const float* zp = (const float*)d_in[3];
    const float* bi = (const float*)d_in[4];
    float* out = (float*)d_out;

    k_detect_w<<<1, 256>>>((const int*)q);
    k_prep<<<PREP_BLKS, 256>>>(q, x, sc, zp);

    cudaFuncSetAttribute(k_gemm, cudaFuncAttributeMaxDynamicSharedMemorySize, SMEM_DYN);
    k_gemm<<<NT * MT, 256, SMEM_DYN>>>(sc, bi, out);
}

// round 14
// speedup vs baseline: 6.1972x; 1.0581x over previous
#include <cuda_runtime.h>
#include <cuda_fp16.h>
#include <cstdint>

// ---------------------------------------------------------------------------
// QuantizedLinear: y = x @ ((q - zp) * s)^T + b
//   y[m,n] = s[n] * (sum_k x[m,k]*q[n,k]) - s[n]*zp[n]*rowsum_x[m] + b[n]
// fp16 single-pass GEMM (q exact in fp16, x rounding ~2^-11), f32 accum via
// mma.sync.m16n8k16 (base-arch features; tcgen05 rejected at compute_103).
// R14 = R10 (best: 1597us) with ONLY GY=16 (halved W DRAM re-reads).
// R13's ks0-first reorder reverted (register-pressure regression).
// Weight buffer arrives as int32 (harness marshalling) — runtime-detected.
// ---------------------------------------------------------------------------

static constexpr int IN_F  = 4096;
static constexpr int OUT_F = 11008;
static constexpr int MROWS = 8192;

static constexpr int BM = 128;
static constexpr int BN = 128;
static constexpr int BK = 64;                 // halves per k-chunk (128 B rows)
static constexpr int KT = IN_F / BK;          // 64
static constexpr int NSTAGE = 3;

static constexpr int A_BYTES = BM * BK * 2;   // 16384
static constexpr int B_BYTES = BN * BK * 2;   // 16384
static constexpr int STAGE_BYTES = A_BYTES + B_BYTES;       // 32768
static constexpr int SMEM_DYN = NSTAGE * STAGE_BYTES;       // 98304 (x2 CTAs)

static constexpr int NT = OUT_F / BN;         // 86
static constexpr int MT = MROWS / BM;         // 64
static constexpr int GY = 16;                 // m-band for L2 reuse
static constexpr int PERB = NT * GY;          // 1376

// fused-prep block ranges
static constexpr int PREP_W_BLKS = OUT_F;          // 11008
static constexpr int PREP_X_BLKS = MROWS;          // 8192
static constexpr int PREP_C_BLKS = OUT_F / 256;    // 43
static constexpr int PREP_BLKS = PREP_W_BLKS + PREP_X_BLKS + PREP_C_BLKS;

// ---------------- device scratch --------------------------------------------
__device__ __align__(16) __half g_W[(size_t)OUT_F * IN_F];   // ~90 MB
__device__ __align__(16) __half g_A[(size_t)MROWS * IN_F];   // ~67 MB
__device__ float g_rowsum[MROWS];
__device__ float g_szp[OUT_F];
__device__ int g_w_is_i32;

// ---------------- helpers ----------------------------------------------------
__device__ __forceinline__ uint32_t smem_u32(const void* p) {
    uint32_t a;
    asm("{ .reg .u64 t; cvta.to.shared.u64 t, %1; cvt.u32.u64 %0, t; }"
        : "=r"(a) : "l"(p));
    return a;
}
__device__ __forceinline__ uint32_t sw128(uint32_t o) { return o ^ ((o >> 3) & 0x70u); }

__device__ __forceinline__ void cp16(uint32_t dst, const void* src) {
    asm volatile("cp.async.cg.shared.global [%0], [%1], 16;" :: "r"(dst), "l"(src));
}
__device__ __forceinline__ void cp_commit() {
    asm volatile("cp.async.commit_group;" ::: "memory");
}
template <int N>
__device__ __forceinline__ void cp_wait() {
    asm volatile("cp.async.wait_group %0;" :: "n"(N) : "memory");
}
__device__ __forceinline__ void ldsm4(uint32_t* a, uint32_t addr) {
    asm volatile("ldmatrix.sync.aligned.m8n8.x4.shared.b16 {%0,%1,%2,%3}, [%4];"
                 : "=r"(a[0]), "=r"(a[1]), "=r"(a[2]), "=r"(a[3]) : "r"(addr));
}
__device__ __forceinline__ void mma16816(float* c, const uint32_t* a,
                                         const uint32_t* b) {
    asm volatile(
        "mma.sync.aligned.m16n8k16.row.col.f32.f16.f16.f32 "
        "{%0,%1,%2,%3}, {%4,%5,%6,%7}, {%8,%9}, {%0,%1,%2,%3};"
        : "+f"(c[0]), "+f"(c[1]), "+f"(c[2]), "+f"(c[3])
        : "r"(a[0]), "r"(a[1]), "r"(a[2]), "r"(a[3]), "r"(b[0]), "r"(b[1]));
}

// ---------------- dtype detection --------------------------------------------
__global__ void k_detect_w(const int* __restrict__ q) {
    __shared__ int cnt;
    if (threadIdx.x == 0) cnt = 0;
    __syncthreads();
    int v = q[threadIdx.x];
    if (v >= -128 && v <= 127) atomicAdd(&cnt, 1);
    __syncthreads();
    if (threadIdx.x == 0) g_w_is_i32 = (cnt >= 200) ? 1 : 0;
}

// ---------------- fused prep kernel -------------------------------------------
__global__ void k_prep(const void* __restrict__ qraw,
                       const float* __restrict__ x,
                       const float* __restrict__ sc,
                       const float* __restrict__ zp) {
    const int b = blockIdx.x;
    const int t = threadIdx.x;

    if (b < PREP_W_BLKS) {
        size_t base = ((size_t)b * 256 + t) * 16;
        __half o[16];
        if (g_w_is_i32) {
            const int4* p = reinterpret_cast<const int4*>(
                reinterpret_cast<const int*>(qraw) + base);
#pragma unroll
            for (int u = 0; u < 4; ++u) {
                int4 v = p[u];
                o[u * 4 + 0] = __float2half_rn((float)v.x);
                o[u * 4 + 1] = __float2half_rn((float)v.y);
                o[u * 4 + 2] = __float2half_rn((float)v.z);
                o[u * 4 + 3] = __float2half_rn((float)v.w);
            }
        } else {
            int4 v = *reinterpret_cast<const int4*>(
                reinterpret_cast<const int8_t*>(qraw) + base);
            const int8_t* c = reinterpret_cast<const int8_t*>(&v);
#pragma unroll
            for (int k = 0; k < 16; ++k) o[k] = __float2half_rn((float)c[k]);
        }
        *reinterpret_cast<int4*>(&g_W[base])     = *reinterpret_cast<const int4*>(&o[0]);
        *reinterpret_cast<int4*>(&g_W[base + 8]) = *reinterpret_cast<const int4*>(&o[8]);
        return;
    }

    if (b < PREP_W_BLKS + PREP_X_BLKS) {
        const int row = b - PREP_W_BLKS;
        const float4* xr = reinterpret_cast<const float4*>(x + (size_t)row * IN_F);
        float s = 0.f;
#pragma unroll
        for (int j = 0; j < 4; ++j) {
            int idx = t + j * 256;
            float4 v = xr[idx];
            s += (v.x + v.y) + (v.z + v.w);
            __half h[4] = {__float2half_rn(v.x), __float2half_rn(v.y),
                           __float2half_rn(v.z), __float2half_rn(v.w)};
            *reinterpret_cast<uint2*>(&g_A[(size_t)row * IN_F + (size_t)idx * 4]) =
                *reinterpret_cast<const uint2*>(h);
        }
#pragma unroll
        for (int o = 16; o > 0; o >>= 1) s += __shfl_xor_sync(0xFFFFFFFFu, s, o);
        __shared__ float ws[8];
        if ((t & 31) == 0) ws[t >> 5] = s;
        __syncthreads();
        if (t == 0) {
            float tot = 0.f;
#pragma unroll
            for (int k = 0; k < 8; ++k) tot += ws[k];
            g_rowsum[row] = tot;
        }
        return;
    }

    int n = (b - PREP_W_BLKS - PREP_X_BLKS) * 256 + t;
    g_szp[n] = sc[n] * zp[n];
}

// ---------------- GEMM ---------------------------------------------------------
__global__ void __launch_bounds__(256, 2)
k_gemm(const float* __restrict__ scale, const float* __restrict__ bias,
       float* __restrict__ out) {
    extern __shared__ __align__(1024) char smem[];
    const uint32_t sb = smem_u32(smem);
    const int tid = threadIdx.x;
    const int wid = tid >> 5;
    const int lane = tid & 31;
    const int mw = wid & 3;        // warp row (0..3), 32 rows each
    const int nw = wid >> 2;       // warp col (0..1), 64 cols each

    // grid swizzle: 16-row m-bands, n fastest within a band
    const int chunk = blockIdx.x / PERB;
    const int rem = blockIdx.x % PERB;
    const int nb = rem / GY;
    const int mb = chunk * GY + (rem % GY);
    const size_t mBase = (size_t)mb * BM;
    const size_t nBase = (size_t)nb * BN;

    const size_t ROWB = (size_t)IN_F * 2;      // bytes per gmem row
    const char* gA = reinterpret_cast<const char*>(g_A) + mBase * ROWB;
    const char* gB = reinterpret_cast<const char*>(g_W) + nBase * ROWB;

    auto issue_stage = [&](int ki, int slot) {
        uint32_t st = sb + slot * STAGE_BYTES;
        const char* pA = gA + (size_t)ki * 128;
        const char* pB = gB + (size_t)ki * 128;
#pragma unroll
        for (int u = 0; u < 4; ++u) {
            int v = tid + u * 256;
            int r = v >> 3, sg = v & 7;
            uint32_t so = sw128((uint32_t)(r * 128 + sg * 16));
            size_t go = (size_t)r * ROWB + (size_t)sg * 16;
            cp16(st + so, pA + go);
            cp16(st + A_BYTES + so, pB + go);
        }
    };

    float acc[2][8][4];
#pragma unroll
    for (int i = 0; i < 2; ++i)
#pragma unroll
        for (int j = 0; j < 8; ++j)
#pragma unroll
            for (int k = 0; k < 4; ++k) acc[i][j][k] = 0.f;

#pragma unroll
    for (int s = 0; s < NSTAGE - 1; ++s) { issue_stage(s, s); cp_commit(); }

    // A frags (x4 non-trans): row = mw*32 + mi*16 + (lane&15), khalf = lane>>4
    const uint32_t aOff = (uint32_t)(mw * 32 + (lane & 15)) * 128 + ((lane >> 4) << 4);
    // B frags (x4 non-trans): g=lane>>3 ->
    //   (n0-7,k0-7),(n0-7,k8-15),(n8-15,k0-7),(n8-15,k8-15)
    const uint32_t g4 = (uint32_t)(lane >> 3);
    const uint32_t bOff =
        (uint32_t)(nw * 64 + ((g4 >> 1) << 3) + (lane & 7)) * 128 + ((g4 & 1) << 4);

#pragma unroll 1
    for (int k = 0; k < KT; ++k) {
        cp_wait<NSTAGE - 2>();
        __syncthreads();
        if (k + NSTAGE - 1 < KT) {
            int kn = k + NSTAGE - 1;
            issue_stage(kn, kn % NSTAGE);
        }
        cp_commit();

        const uint32_t st = sb + (uint32_t)(k % NSTAGE) * STAGE_BYTES;
#pragma unroll
        for (int ks = 0; ks < 4; ++ks) {
            uint32_t a[2][4];
#pragma unroll
            for (int mi = 0; mi < 2; ++mi)
                ldsm4(a[mi], st + sw128(aOff + (uint32_t)(mi * 2048 + ks * 32)));
            uint32_t b[4][4];
#pragma unroll
            for (int p = 0; p < 4; ++p)
                ldsm4(b[p],
                      st + A_BYTES + sw128(bOff + (uint32_t)(p * 2048 + ks * 32)));
#pragma unroll
            for (int mi = 0; mi < 2; ++mi)
#pragma unroll
                for (int p = 0; p < 4; ++p) {
                    mma16816(acc[mi][p * 2 + 0], a[mi], &b[p][0]);
                    mma16816(acc[mi][p * 2 + 1], a[mi], &b[p][2]);
                }
        }
    }

    __syncthreads();

    // epilogue coefficients in (now free) smem
    float* sSc = reinterpret_cast<float*>(smem);
    float* sZp = sSc + BN;
    float* sBi = sZp + BN;
    for (int v = tid; v < BN; v += 256) {
        int n = (int)nBase + v;
        sSc[v] = scale[n];
        sZp[v] = g_szp[n];
        sBi[v] = bias[n];
    }
    __syncthreads();

    const int rBase = (int)mBase + mw * 32 + (lane >> 2);
    const int cq = (lane & 3) * 2;
#pragma unroll
    for (int mi = 0; mi < 2; ++mi) {
        const int r0 = rBase + mi * 16;
        const float rs0 = g_rowsum[r0];
        const float rs1 = g_rowsum[r0 + 8];
        float* o0 = out + (size_t)r0 * OUT_F + nBase;
        float* o1 = out + (size_t)(r0 + 8) * OUT_F + nBase;
#pragma unroll
        for (int p = 0; p < 4; ++p) {
#pragma unroll
            for (int h = 0; h < 2; ++h) {
                const float* c = acc[mi][p * 2 + h];
                const int col = nw * 64 + p * 16 + h * 8 + cq;
                float2 v0, v1;
                v0.x = fmaf(c[0], sSc[col],     fmaf(-rs0, sZp[col],     sBi[col]));
                v0.y = fmaf(c[1], sSc[col + 1], fmaf(-rs0, sZp[col + 1], sBi[col + 1]));
                v1.x = fmaf(c[2], sSc[col],     fmaf(-rs1, sZp[col],     sBi[col]));
                v1.y = fmaf(c[3], sSc[col + 1], fmaf(-rs1, sZp[col + 1], sBi[col + 1]));
                *reinterpret_cast<float2*>(o0 + col) = v0;
                *reinterpret_cast<float2*>(o1 + col) = v1;
            }
        }
    }
}

// ---------------- launch -------------------------------------------------------
extern "C" void kernel_launch(void* const* d_in, const int* in_sizes, int n_in,
                              void* d_out, int out_size) {
    const float* x  = (const float*)d_in[0];
    const void*  q  = d_in[1];
    const float* sc = (const float*)d_in[2];
    const float* zp = (const float*)d_in[3];
    const float* bi = (const float*)d_in[4];
    float* out = (float*)d_out;

    k_detect_w<<<1, 256>>>((const int*)q);
    k_prep<<<PREP_BLKS, 256>>>(q, x, sc, zp);

    cudaFuncSetAttribute(k_gemm, cudaFuncAttributeMaxDynamicSharedMemorySize, SMEM_DYN);
    k_gemm<<<NT * MT, 256, SMEM_DYN>>>(sc, bi, out);
}

// round 15
// speedup vs baseline: 6.2014x; 1.0007x over previous
#include <cuda_runtime.h>
#include <cuda_fp16.h>
#include <cstdint>

// ---------------------------------------------------------------------------
// QuantizedLinear: y = x @ ((q - zp) * s)^T + b
//   y[m,n] = s[n] * (sum_k x[m,k]*q[n,k]) - s[n]*zp[n]*rowsum_x[m] + b[n]
// fp16 single-pass GEMM (q exact in fp16, x rounding ~2^-11), f32 accum via
// mma.sync.m16n8k16 (base-arch features; tcgen05 rejected at compute_103).
// R15 = R14 + epilogue coefficients staged into a DEDICATED smem region in
// the prologue (overlapped with pipeline fill) -> both post-loop barriers and
// the exposed tail gmem latency removed. rowsum prefetched to registers.
// Weight buffer arrives as int32 (harness marshalling) — runtime-detected.
// ---------------------------------------------------------------------------

static constexpr int IN_F  = 4096;
static constexpr int OUT_F = 11008;
static constexpr int MROWS = 8192;

static constexpr int BM = 128;
static constexpr int BN = 128;
static constexpr int BK = 64;                 // halves per k-chunk (128 B rows)
static constexpr int KT = IN_F / BK;          // 64
static constexpr int NSTAGE = 3;

static constexpr int A_BYTES = BM * BK * 2;   // 16384
static constexpr int B_BYTES = BN * BK * 2;   // 16384
static constexpr int STAGE_BYTES = A_BYTES + B_BYTES;       // 32768
static constexpr int COEF_OFF = NSTAGE * STAGE_BYTES;       // 98304
static constexpr int SMEM_DYN = COEF_OFF + 3 * BN * 4;      // 99840 (x2 CTAs ok)

static constexpr int NT = OUT_F / BN;         // 86
static constexpr int MT = MROWS / BM;         // 64
static constexpr int GY = 16;                 // m-band for L2 reuse
static constexpr int PERB = NT * GY;          // 1376

// fused-prep block ranges
static constexpr int PREP_W_BLKS = OUT_F;          // 11008
static constexpr int PREP_X_BLKS = MROWS;          // 8192
static constexpr int PREP_C_BLKS = OUT_F / 256;    // 43
static constexpr int PREP_BLKS = PREP_W_BLKS + PREP_X_BLKS + PREP_C_BLKS;

// ---------------- device scratch --------------------------------------------
__device__ __align__(16) __half g_W[(size_t)OUT_F * IN_F];   // ~90 MB
__device__ __align__(16) __half g_A[(size_t)MROWS * IN_F];   // ~67 MB
__device__ float g_rowsum[MROWS];
__device__ float g_szp[OUT_F];
__device__ int g_w_is_i32;

// ---------------- helpers ----------------------------------------------------
__device__ __forceinline__ uint32_t smem_u32(const void* p) {
    uint32_t a;
    asm("{ .reg .u64 t; cvta.to.shared.u64 t, %1; cvt.u32.u64 %0, t; }"
        : "=r"(a) : "l"(p));
    return a;
}
__device__ __forceinline__ uint32_t sw128(uint32_t o) { return o ^ ((o >> 3) & 0x70u); }

__device__ __forceinline__ void cp16(uint32_t dst, const void* src) {
    asm volatile("cp.async.cg.shared.global [%0], [%1], 16;" :: "r"(dst), "l"(src));
}
__device__ __forceinline__ void cp_commit() {
    asm volatile("cp.async.commit_group;" ::: "memory");
}
template <int N>
__device__ __forceinline__ void cp_wait() {
    asm volatile("cp.async.wait_group %0;" :: "n"(N) : "memory");
}
__device__ __forceinline__ void ldsm4(uint32_t* a, uint32_t addr) {
    asm volatile("ldmatrix.sync.aligned.m8n8.x4.shared.b16 {%0,%1,%2,%3}, [%4];"
                 : "=r"(a[0]), "=r"(a[1]), "=r"(a[2]), "=r"(a[3]) : "r"(addr));
}
__device__ __forceinline__ void mma16816(float* c, const uint32_t* a,
                                         const uint32_t* b) {
    asm volatile(
        "mma.sync.aligned.m16n8k16.row.col.f32.f16.f16.f32 "
        "{%0,%1,%2,%3}, {%4,%5,%6,%7}, {%8,%9}, {%0,%1,%2,%3};"
        : "+f"(c[0]), "+f"(c[1]), "+f"(c[2]), "+f"(c[3])
        : "r"(a[0]), "r"(a[1]), "r"(a[2]), "r"(a[3]), "r"(b[0]), "r"(b[1]));
}

// ---------------- dtype detection --------------------------------------------
__global__ void k_detect_w(const int* __restrict__ q) {
    __shared__ int cnt;
    if (threadIdx.x == 0) cnt = 0;
    __syncthreads();
    int v = q[threadIdx.x];
    if (v >= -128 && v <= 127) atomicAdd(&cnt, 1);
    __syncthreads();
    if (threadIdx.x == 0) g_w_is_i32 = (cnt >= 200) ? 1 : 0;
}

// ---------------- fused prep kernel -------------------------------------------
__global__ void k_prep(const void* __restrict__ qraw,
                       const float* __restrict__ x,
                       const float* __restrict__ sc,
                       const float* __restrict__ zp) {
    const int b = blockIdx.x;
    const int t = threadIdx.x;

    if (b < PREP_W_BLKS) {
        size_t base = ((size_t)b * 256 + t) * 16;
        __half o[16];
        if (g_w_is_i32) {
            const int4* p = reinterpret_cast<const int4*>(
                reinterpret_cast<const int*>(qraw) + base);
#pragma unroll
            for (int u = 0; u < 4; ++u) {
                int4 v = p[u];
                o[u * 4 + 0] = __float2half_rn((float)v.x);
                o[u * 4 + 1] = __float2half_rn((float)v.y);
                o[u * 4 + 2] = __float2half_rn((float)v.z);
                o[u * 4 + 3] = __float2half_rn((float)v.w);
            }
        } else {
            int4 v = *reinterpret_cast<const int4*>(
                reinterpret_cast<const int8_t*>(qraw) + base);
            const int8_t* c = reinterpret_cast<const int8_t*>(&v);
#pragma unroll
            for (int k = 0; k < 16; ++k) o[k] = __float2half_rn((float)c[k]);
        }
        *reinterpret_cast<int4*>(&g_W[base])     = *reinterpret_cast<const int4*>(&o[0]);
        *reinterpret_cast<int4*>(&g_W[base + 8]) = *reinterpret_cast<const int4*>(&o[8]);
        return;
    }

    if (b < PREP_W_BLKS + PREP_X_BLKS) {
        const int row = b - PREP_W_BLKS;
        const float4* xr = reinterpret_cast<const float4*>(x + (size_t)row * IN_F);
        float s = 0.f;
#pragma unroll
        for (int j = 0; j < 4; ++j) {
            int idx = t + j * 256;
            float4 v = xr[idx];
            s += (v.x + v.y) + (v.z + v.w);
            __half h[4] = {__float2half_rn(v.x), __float2half_rn(v.y),
                           __float2half_rn(v.z), __float2half_rn(v.w)};
            *reinterpret_cast<uint2*>(&g_A[(size_t)row * IN_F + (size_t)idx * 4]) =
                *reinterpret_cast<const uint2*>(h);
        }
#pragma unroll
        for (int o = 16; o > 0; o >>= 1) s += __shfl_xor_sync(0xFFFFFFFFu, s, o);
        __shared__ float ws[8];
        if ((t & 31) == 0) ws[t >> 5] = s;
        __syncthreads();
        if (t == 0) {
            float tot = 0.f;
#pragma unroll
            for (int k = 0; k < 8; ++k) tot += ws[k];
            g_rowsum[row] = tot;
        }
        return;
    }

    int n = (b - PREP_W_BLKS - PREP_X_BLKS) * 256 + t;
    g_szp[n] = sc[n] * zp[n];
}

// ---------------- GEMM ---------------------------------------------------------
__global__ void __launch_bounds__(256, 2)
k_gemm(const float* __restrict__ scale, const float* __restrict__ bias,
       float* __restrict__ out) {
    extern __shared__ __align__(1024) char smem[];
    const uint32_t sb = smem_u32(smem);
    const int tid = threadIdx.x;
    const int wid = tid >> 5;
    const int lane = tid & 31;
    const int mw = wid & 3;        // warp row (0..3), 32 rows each
    const int nw = wid >> 2;       // warp col (0..1), 64 cols each

    // grid swizzle: 16-row m-bands, n fastest within a band
    const int chunk = blockIdx.x / PERB;
    const int rem = blockIdx.x % PERB;
    const int nb = rem / GY;
    const int mb = chunk * GY + (rem % GY);
    const size_t mBase = (size_t)mb * BM;
    const size_t nBase = (size_t)nb * BN;

    const size_t ROWB = (size_t)IN_F * 2;      // bytes per gmem row
    const char* gA = reinterpret_cast<const char*>(g_A) + mBase * ROWB;
    const char* gB = reinterpret_cast<const char*>(g_W) + nBase * ROWB;

    auto issue_stage = [&](int ki, int slot) {
        uint32_t st = sb + slot * STAGE_BYTES;
        const char* pA = gA + (size_t)ki * 128;
        const char* pB = gB + (size_t)ki * 128;
#pragma unroll
        for (int u = 0; u < 4; ++u) {
            int v = tid + u * 256;
            int r = v >> 3, sg = v & 7;
            uint32_t so = sw128((uint32_t)(r * 128 + sg * 16));
            size_t go = (size_t)r * ROWB + (size_t)sg * 16;
            cp16(st + so, pA + go);
            cp16(st + A_BYTES + so, pB + go);
        }
    };

    float acc[2][8][4];
#pragma unroll
    for (int i = 0; i < 2; ++i)
#pragma unroll
        for (int j = 0; j < 8; ++j)
#pragma unroll
            for (int k = 0; k < 4; ++k) acc[i][j][k] = 0.f;

#pragma unroll
    for (int s = 0; s < NSTAGE - 1; ++s) { issue_stage(s, s); cp_commit(); }

    // ---- stage epilogue coefficients NOW (dedicated region, overlapped with
    //      pipeline fill; visible to all threads after the first loop barrier)
    float* sSc = reinterpret_cast<float*>(smem + COEF_OFF);
    float* sZp = sSc + BN;
    float* sBi = sZp + BN;
    if (tid < BN) {
        int n = (int)nBase + tid;
        sSc[tid] = scale[n];
        sZp[tid] = g_szp[n];
        sBi[tid] = bias[n];
    }

    // rowsum prefetch (4 regs)
    const int rBase = (int)mBase + mw * 32 + (lane >> 2);
    const float rsum[4] = {g_rowsum[rBase],      g_rowsum[rBase + 8],
                           g_rowsum[rBase + 16], g_rowsum[rBase + 24]};

    // A frags (x4 non-trans): row = mw*32 + mi*16 + (lane&15), khalf = lane>>4
    const uint32_t aOff = (uint32_t)(mw * 32 + (lane & 15)) * 128 + ((lane >> 4) << 4);
    // B frags (x4 non-trans): g=lane>>3 ->
    //   (n0-7,k0-7),(n0-7,k8-15),(n8-15,k0-7),(n8-15,k8-15)
    const uint32_t g4 = (uint32_t)(lane >> 3);
    const uint32_t bOff =
        (uint32_t)(nw * 64 + ((g4 >> 1) << 3) + (lane & 7)) * 128 + ((g4 & 1) << 4);

#pragma unroll 1
    for (int k = 0; k < KT; ++k) {
        cp_wait<NSTAGE - 2>();
        __syncthreads();
        if (k + NSTAGE - 1 < KT) {
            int kn = k + NSTAGE - 1;
            issue_stage(kn, kn % NSTAGE);
        }
        cp_commit();

        const uint32_t st = sb + (uint32_t)(k % NSTAGE) * STAGE_BYTES;
#pragma unroll
        for (int ks = 0; ks < 4; ++ks) {
            uint32_t a[2][4];
#pragma unroll
            for (int mi = 0; mi < 2; ++mi)
                ldsm4(a[mi], st + sw128(aOff + (uint32_t)(mi * 2048 + ks * 32)));
            uint32_t b[4][4];
#pragma unroll
            for (int p = 0; p < 4; ++p)
                ldsm4(b[p],
                      st + A_BYTES + sw128(bOff + (uint32_t)(p * 2048 + ks * 32)));
#pragma unroll
            for (int mi = 0; mi < 2; ++mi)
#pragma unroll
                for (int p = 0; p < 4; ++p) {
                    mma16816(acc[mi][p * 2 + 0], a[mi], &b[p][0]);
                    mma16816(acc[mi][p * 2 + 1], a[mi], &b[p][2]);
                }
        }
    }

    // ---- epilogue: no barriers needed (coefficients staged in prologue,
    //      own smem region; accumulators are thread-private)
    const int cq = (lane & 3) * 2;
#pragma unroll
    for (int mi = 0; mi < 2; ++mi) {
        const int r0 = rBase + mi * 16;
        const float rs0 = rsum[mi * 2 + 0];
        const float rs1 = rsum[mi * 2 + 1];
        float* o0 = out + (size_t)r0 * OUT_F + nBase;
        float* o1 = out + (size_t)(r0 + 8) * OUT_F + nBase;
#pragma unroll
        for (int p = 0; p < 4; ++p) {
#pragma unroll
            for (int h = 0; h < 2; ++h) {
                const float* c = acc[mi][p * 2 + h];
                const int col = nw * 64 + p * 16 + h * 8 + cq;
                float2 v0, v1;
                v0.x = fmaf(c[0], sSc[col],     fmaf(-rs0, sZp[col],     sBi[col]));
                v0.y = fmaf(c[1], sSc[col + 1], fmaf(-rs0, sZp[col + 1], sBi[col + 1]));
                v1.x = fmaf(c[2], sSc[col],     fmaf(-rs1, sZp[col],     sBi[col]));
                v1.y = fmaf(c[3], sSc[col + 1], fmaf(-rs1, sZp[col + 1], sBi[col + 1]));
                *reinterpret_cast<float2*>(o0 + col) = v0;
                *reinterpret_cast<float2*>(o1 + col) = v1;
            }
        }
    }
}

// ---------------- launch -------------------------------------------------------
extern "C" void kernel_launch(void* const* d_in, const int* in_sizes, int n_in,
                              void* d_out, int out_size) {
    const float* x  = (const float*)d_in[0];
    const void*  q  = d_in[1];
    const float* sc = (const float*)d_in[2];
    const float* zp = (const float*)d_in[3];
    const float* bi = (const float*)d_in[4];
    float* out = (float*)d_out;

    k_detect_w<<<1, 256>>>((const int*)q);
    k_prep<<<PREP_BLKS, 256>>>(q, x, sc, zp);

    cudaFuncSetAttribute(k_gemm, cudaFuncAttributeMaxDynamicSharedMemorySize, SMEM_DYN);
    k_gemm<<<NT * MT, 256, SMEM_DYN>>>(sc, bi, out);
}

// round 16
// speedup vs baseline: 6.2101x; 1.0014x over previous
#include <cuda_runtime.h>
#include <cuda_fp16.h>
#include <cstdint>

// ---------------------------------------------------------------------------
// QuantizedLinear: y = x @ ((q - zp) * s)^T + b
//   y[m,n] = s[n] * (sum_k x[m,k]*q[n,k]) - s[n]*zp[n]*rowsum_x[m] + b[n]
// fp16 single-pass GEMM (q exact in fp16, x rounding ~2^-11), f32 accum via
// mma.sync.m16n8k16 (base-arch features; tcgen05 rejected at compute_103).
// R16 = R15 GEMM (tied-best) + weight-dtype detection folded into k_prep
// (per-block probe of the first 1KB, L2-broadcast) -> detect launch removed.
// Weight buffer arrives as int32 (harness marshalling) — runtime-detected.
// ---------------------------------------------------------------------------

static constexpr int IN_F  = 4096;
static constexpr int OUT_F = 11008;
static constexpr int MROWS = 8192;

static constexpr int BM = 128;
static constexpr int BN = 128;
static constexpr int BK = 64;                 // halves per k-chunk (128 B rows)
static constexpr int KT = IN_F / BK;          // 64
static constexpr int NSTAGE = 3;

static constexpr int A_BYTES = BM * BK * 2;   // 16384
static constexpr int B_BYTES = BN * BK * 2;   // 16384
static constexpr int STAGE_BYTES = A_BYTES + B_BYTES;       // 32768
static constexpr int COEF_OFF = NSTAGE * STAGE_BYTES;       // 98304
static constexpr int SMEM_DYN = COEF_OFF + 3 * BN * 4;      // 99840 (x2 CTAs ok)

static constexpr int NT = OUT_F / BN;         // 86
static constexpr int MT = MROWS / BM;         // 64
static constexpr int GY = 16;                 // m-band for L2 reuse
static constexpr int PERB = NT * GY;          // 1376

// fused-prep block ranges
static constexpr int PREP_W_BLKS = OUT_F;          // 11008
static constexpr int PREP_X_BLKS = MROWS;          // 8192
static constexpr int PREP_C_BLKS = OUT_F / 256;    // 43
static constexpr int PREP_BLKS = PREP_W_BLKS + PREP_X_BLKS + PREP_C_BLKS;

// ---------------- device scratch --------------------------------------------
__device__ __align__(16) __half g_W[(size_t)OUT_F * IN_F];   // ~90 MB
__device__ __align__(16) __half g_A[(size_t)MROWS * IN_F];   // ~67 MB
__device__ float g_rowsum[MROWS];
__device__ float g_szp[OUT_F];

// ---------------- helpers ----------------------------------------------------
__device__ __forceinline__ uint32_t smem_u32(const void* p) {
    uint32_t a;
    asm("{ .reg .u64 t; cvta.to.shared.u64 t, %1; cvt.u32.u64 %0, t; }"
        : "=r"(a) : "l"(p));
    return a;
}
__device__ __forceinline__ uint32_t sw128(uint32_t o) { return o ^ ((o >> 3) & 0x70u); }

__device__ __forceinline__ void cp16(uint32_t dst, const void* src) {
    asm volatile("cp.async.cg.shared.global [%0], [%1], 16;" :: "r"(dst), "l"(src));
}
__device__ __forceinline__ void cp_commit() {
    asm volatile("cp.async.commit_group;" ::: "memory");
}
template <int N>
__device__ __forceinline__ void cp_wait() {
    asm volatile("cp.async.wait_group %0;" :: "n"(N) : "memory");
}
__device__ __forceinline__ void ldsm4(uint32_t* a, uint32_t addr) {
    asm volatile("ldmatrix.sync.aligned.m8n8.x4.shared.b16 {%0,%1,%2,%3}, [%4];"
                 : "=r"(a[0]), "=r"(a[1]), "=r"(a[2]), "=r"(a[3]) : "r"(addr));
}
__device__ __forceinline__ void mma16816(float* c, const uint32_t* a,
                                         const uint32_t* b) {
    asm volatile(
        "mma.sync.aligned.m16n8k16.row.col.f32.f16.f16.f32 "
        "{%0,%1,%2,%3}, {%4,%5,%6,%7}, {%8,%9}, {%0,%1,%2,%3};"
        : "+f"(c[0]), "+f"(c[1]), "+f"(c[2]), "+f"(c[3])
        : "r"(a[0]), "r"(a[1]), "r"(a[2]), "r"(a[3]), "r"(b[0]), "r"(b[1]));
}

// ---------------- fused prep kernel (with inline dtype detection) -------------
__global__ void k_prep(const void* __restrict__ qraw,
                       const float* __restrict__ x,
                       const float* __restrict__ sc,
                       const float* __restrict__ zp) {
    const int b = blockIdx.x;
    const int t = threadIdx.x;

    if (b < PREP_W_BLKS) {
        // ---- inline detection: probe the FIRST 256 i32 words (same 1KB for
        //      every block -> L2 broadcast; safe under both layouts).
        //      i32 layout: all in [-128,127]. i8 layout: prob ~2^-24 per word.
        __shared__ int cnt;
        if (t == 0) cnt = 0;
        __syncthreads();
        {
            int v = reinterpret_cast<const int*>(qraw)[t];
            unsigned m = __ballot_sync(0xFFFFFFFFu, v >= -128 && v <= 127);
            if ((t & 31) == 0) atomicAdd(&cnt, __popc(m));
        }
        __syncthreads();
        const bool is_i32 = (cnt >= 200);

        size_t base = ((size_t)b * 256 + t) * 16;
        __half o[16];
        if (is_i32) {
            const int4* p = reinterpret_cast<const int4*>(
                reinterpret_cast<const int*>(qraw) + base);
#pragma unroll
            for (int u = 0; u < 4; ++u) {
                int4 v = p[u];
                o[u * 4 + 0] = __float2half_rn((float)v.x);
                o[u * 4 + 1] = __float2half_rn((float)v.y);
                o[u * 4 + 2] = __float2half_rn((float)v.z);
                o[u * 4 + 3] = __float2half_rn((float)v.w);
            }
        } else {
            int4 v = *reinterpret_cast<const int4*>(
                reinterpret_cast<const int8_t*>(qraw) + base);
            const int8_t* c = reinterpret_cast<const int8_t*>(&v);
#pragma unroll
            for (int k = 0; k < 16; ++k) o[k] = __float2half_rn((float)c[k]);
        }
        *reinterpret_cast<int4*>(&g_W[base])     = *reinterpret_cast<const int4*>(&o[0]);
        *reinterpret_cast<int4*>(&g_W[base + 8]) = *reinterpret_cast<const int4*>(&o[8]);
        return;
    }

    if (b < PREP_W_BLKS + PREP_X_BLKS) {
        const int row = b - PREP_W_BLKS;
        const float4* xr = reinterpret_cast<const float4*>(x + (size_t)row * IN_F);
        float s = 0.f;
#pragma unroll
        for (int j = 0; j < 4; ++j) {
            int idx = t + j * 256;
            float4 v = xr[idx];
            s += (v.x + v.y) + (v.z + v.w);
            __half h[4] = {__float2half_rn(v.x), __float2half_rn(v.y),
                           __float2half_rn(v.z), __float2half_rn(v.w)};
            *reinterpret_cast<uint2*>(&g_A[(size_t)row * IN_F + (size_t)idx * 4]) =
                *reinterpret_cast<const uint2*>(h);
        }
#pragma unroll
        for (int o = 16; o > 0; o >>= 1) s += __shfl_xor_sync(0xFFFFFFFFu, s, o);
        __shared__ float ws[8];
        if ((t & 31) == 0) ws[t >> 5] = s;
        __syncthreads();
        if (t == 0) {
            float tot = 0.f;
#pragma unroll
            for (int k = 0; k < 8; ++k) tot += ws[k];
            g_rowsum[row] = tot;
        }
        return;
    }

    int n = (b - PREP_W_BLKS - PREP_X_BLKS) * 256 + t;
    g_szp[n] = sc[n] * zp[n];
}

// ---------------- GEMM ---------------------------------------------------------
__global__ void __launch_bounds__(256, 2)
k_gemm(const float* __restrict__ scale, const float* __restrict__ bias,
       float* __restrict__ out) {
    extern __shared__ __align__(1024) char smem[];
    const uint32_t sb = smem_u32(smem);
    const int tid = threadIdx.x;
    const int wid = tid >> 5;
    const int lane = tid & 31;
    const int mw = wid & 3;        // warp row (0..3), 32 rows each
    const int nw = wid >> 2;       // warp col (0..1), 64 cols each

    // grid swizzle: 16-row m-bands, n fastest within a band
    const int chunk = blockIdx.x / PERB;
    const int rem = blockIdx.x % PERB;
    const int nb = rem / GY;
    const int mb = chunk * GY + (rem % GY);
    const size_t mBase = (size_t)mb * BM;
    const size_t nBase = (size_t)nb * BN;

    const size_t ROWB = (size_t)IN_F * 2;      // bytes per gmem row
    const char* gA = reinterpret_cast<const char*>(g_A) + mBase * ROWB;
    const char* gB = reinterpret_cast<const char*>(g_W) + nBase * ROWB;

    auto issue_stage = [&](int ki, int slot) {
        uint32_t st = sb + slot * STAGE_BYTES;
        const char* pA = gA + (size_t)ki * 128;
        const char* pB = gB + (size_t)ki * 128;
#pragma unroll
        for (int u = 0; u < 4; ++u) {
            int v = tid + u * 256;
            int r = v >> 3, sg = v & 7;
            uint32_t so = sw128((uint32_t)(r * 128 + sg * 16));
            size_t go = (size_t)r * ROWB + (size_t)sg * 16;
            cp16(st + so, pA + go);
            cp16(st + A_BYTES + so, pB + go);
        }
    };

    float acc[2][8][4];
#pragma unroll
    for (int i = 0; i < 2; ++i)
#pragma unroll
        for (int j = 0; j < 8; ++j)
#pragma unroll
            for (int k = 0; k < 4; ++k) acc[i][j][k] = 0.f;

#pragma unroll
    for (int s = 0; s < NSTAGE - 1; ++s) { issue_stage(s, s); cp_commit(); }

    // ---- stage epilogue coefficients in the prologue (dedicated region;
    //      visible to all threads after the first in-loop barrier)
    float* sSc = reinterpret_cast<float*>(smem + COEF_OFF);
    float* sZp = sSc + BN;
    float* sBi = sZp + BN;
    if (tid < BN) {
        int n = (int)nBase + tid;
        sSc[tid] = scale[n];
        sZp[tid] = g_szp[n];
        sBi[tid] = bias[n];
    }

    // rowsum prefetch (4 regs)
    const int rBase = (int)mBase + mw * 32 + (lane >> 2);
    const float rsum[4] = {g_rowsum[rBase],      g_rowsum[rBase + 8],
                           g_rowsum[rBase + 16], g_rowsum[rBase + 24]};

    // A frags (x4 non-trans): row = mw*32 + mi*16 + (lane&15), khalf = lane>>4
    const uint32_t aOff = (uint32_t)(mw * 32 + (lane & 15)) * 128 + ((lane >> 4) << 4);
    // B frags (x4 non-trans): g=lane>>3 ->
    //   (n0-7,k0-7),(n0-7,k8-15),(n8-15,k0-7),(n8-15,k8-15)
    const uint32_t g4 = (uint32_t)(lane >> 3);
    const uint32_t bOff =
        (uint32_t)(nw * 64 + ((g4 >> 1) << 3) + (lane & 7)) * 128 + ((g4 & 1) << 4);

#pragma unroll 1
    for (int k = 0; k < KT; ++k) {
        cp_wait<NSTAGE - 2>();
        __syncthreads();
        if (k + NSTAGE - 1 < KT) {
            int kn = k + NSTAGE - 1;
            issue_stage(kn, kn % NSTAGE);
        }
        cp_commit();

        const uint32_t st = sb + (uint32_t)(k % NSTAGE) * STAGE_BYTES;
#pragma unroll
        for (int ks = 0; ks < 4; ++ks) {
            uint32_t a[2][4];
#pragma unroll
            for (int mi = 0; mi < 2; ++mi)
                ldsm4(a[mi], st + sw128(aOff + (uint32_t)(mi * 2048 + ks * 32)));
            uint32_t b[4][4];
#pragma unroll
            for (int p = 0; p < 4; ++p)
                ldsm4(b[p],
                      st + A_BYTES + sw128(bOff + (uint32_t)(p * 2048 + ks * 32)));
#pragma unroll
            for (int mi = 0; mi < 2; ++mi)
#pragma unroll
                for (int p = 0; p < 4; ++p) {
                    mma16816(acc[mi][p * 2 + 0], a[mi], &b[p][0]);
                    mma16816(acc[mi][p * 2 + 1], a[mi], &b[p][2]);
                }
        }
    }

    // ---- epilogue: no extra barriers (coefficients staged in prologue)
    const int cq = (lane & 3) * 2;
#pragma unroll
    for (int mi = 0; mi < 2; ++mi) {
        const int r0 = rBase + mi * 16;
        const float rs0 = rsum[mi * 2 + 0];
        const float rs1 = rsum[mi * 2 + 1];
        float* o0 = out + (size_t)r0 * OUT_F + nBase;
        float* o1 = out + (size_t)(r0 + 8) * OUT_F + nBase;
#pragma unroll
        for (int p = 0; p < 4; ++p) {
#pragma unroll
            for (int h = 0; h < 2; ++h) {
                const float* c = acc[mi][p * 2 + h];
                const int col = nw * 64 + p * 16 + h * 8 + cq;
                float2 v0, v1;
                v0.x = fmaf(c[0], sSc[col],     fmaf(-rs0, sZp[col],     sBi[col]));
                v0.y = fmaf(c[1], sSc[col + 1], fmaf(-rs0, sZp[col + 1], sBi[col + 1]));
                v1.x = fmaf(c[2], sSc[col],     fmaf(-rs1, sZp[col],     sBi[col]));
                v1.y = fmaf(c[3], sSc[col + 1], fmaf(-rs1, sZp[col + 1], sBi[col + 1]));
                *reinterpret_cast<float2*>(o0 + col) = v0;
                *reinterpret_cast<float2*>(o1 + col) = v1;
            }
        }
    }
}

// ---------------- launch -------------------------------------------------------
extern "C" void kernel_launch(void* const* d_in, const int* in_sizes, int n_in,
                              void* d_out, int out_size) {
    const float* x  = (const float*)d_in[0];
    const void*  q  = d_in[1];
    const float* sc = (const float*)d_in[2];
    const float* zp = (const float*)d_in[3];
    const float* bi = (const float*)d_in[4];
    float* out = (float*)d_out;

    k_prep<<<PREP_BLKS, 256>>>(q, x, sc, zp);

    cudaFuncSetAttribute(k_gemm, cudaFuncAttributeMaxDynamicSharedMemorySize, SMEM_DYN);
    k_gemm<<<NT * MT, 256, SMEM_DYN>>>(sc, bi, out);
}